// round 15
// baseline (speedup 1.0000x reference)
#include <cuda_runtime.h>
#include <cuda_bf16.h>
#include <cstdint>

// Per-token-group (G=128) dynamic fp8-range quantization.
// x: [M, N] fp32 (bf16-rounded values upcast by harness).
// y = clip(x * 448/amax, +-448) fp32; scale = max(amax,1e-4)/448 per group.
// d_out layout: [y (M*N) || scale (M*N/128)] fp32.
//
// Experiment: MLP_p1=4 (four front-batched LDG.128 per warp) with a register
// cap (__launch_bounds__(256, 8) -> <=32 regs) so occupancy stays at the R8
// level. Isolates the MLP axis from the occupancy confound that sank R9.

#define GROUP_SIZE 128
#define FP8_MAX 448.0f
#define AMAX_FLOOR 1e-4f

__device__ float g_scale_scratch[1 << 20];  // fallback, never used in practice

__device__ __forceinline__ float max4abs(float4 v) {
    return fmaxf(fmaxf(fabsf(v.x), fabsf(v.y)), fmaxf(fabsf(v.z), fabsf(v.w)));
}

__device__ __forceinline__ float4 scale4(float4 v, float s) {
    float4 o;
    o.x = fminf(fmaxf(v.x * s, -FP8_MAX), FP8_MAX);
    o.y = fminf(fmaxf(v.y * s, -FP8_MAX), FP8_MAX);
    o.z = fminf(fmaxf(v.z * s, -FP8_MAX), FP8_MAX);
    o.w = fminf(fmaxf(v.w * s, -FP8_MAX), FP8_MAX);
    return o;
}

// One warp handles FOUR groups; all four 16B loads issue back-to-back.
// Register budget: 4 live float4 (16) + addressing/amax (~10) fits in 32.
// Each group is reduced and stored immediately after its REDUX so outputs
// reuse input registers (no 8-float4 live window).
__global__ void __launch_bounds__(256, 8) quant_fp8_group_kernel(
    const float4* __restrict__ x4,
    float4* __restrict__ y4,
    float* __restrict__ scale,
    int num_groups)
{
    const int warp = threadIdx.x >> 5;
    const int lane = threadIdx.x & 31;
    const int g0 = (blockIdx.x * 8 + warp) * 4;     // first of four groups
    if (g0 >= num_groups) return;

    const size_t base = (size_t)g0 * 32 + (size_t)lane;  // in float4 units

    // Front-batched independent loads (four groups)
    float4 a = x4[base];
    float4 b = x4[base + 32];
    float4 c = x4[base + 64];
    float4 d = x4[base + 96];

    // Reduce + store per group, in load-completion order, minimizing live regs
    unsigned ra = __reduce_max_sync(0xffffffffu, __float_as_uint(max4abs(a)));
    const float amaxA = fmaxf(__uint_as_float(ra), AMAX_FLOOR);
    y4[base] = scale4(a, FP8_MAX / amaxA);

    unsigned rb = __reduce_max_sync(0xffffffffu, __float_as_uint(max4abs(b)));
    const float amaxB = fmaxf(__uint_as_float(rb), AMAX_FLOOR);
    y4[base + 32] = scale4(b, FP8_MAX / amaxB);

    unsigned rc = __reduce_max_sync(0xffffffffu, __float_as_uint(max4abs(c)));
    const float amaxC = fmaxf(__uint_as_float(rc), AMAX_FLOOR);
    y4[base + 64] = scale4(c, FP8_MAX / amaxC);

    unsigned rd = __reduce_max_sync(0xffffffffu, __float_as_uint(max4abs(d)));
    const float amaxD = fmaxf(__uint_as_float(rd), AMAX_FLOOR);
    y4[base + 96] = scale4(d, FP8_MAX / amaxD);

    // One scale per group (lanes 0-3)
    if (lane == 0) scale[g0] = amaxA / FP8_MAX;
    else if (lane == 1 && g0 + 1 < num_groups) scale[g0 + 1] = amaxB / FP8_MAX;
    else if (lane == 2 && g0 + 2 < num_groups) scale[g0 + 2] = amaxC / FP8_MAX;
    else if (lane == 3 && g0 + 3 < num_groups) scale[g0 + 3] = amaxD / FP8_MAX;
}

extern "C" void kernel_launch(void* const* d_in, const int* in_sizes, int n_in,
                              void* d_out, int out_size)
{
    const float* x = (const float*)d_in[0];
    const size_t total = (size_t)in_sizes[0];          // M * N
    const int num_groups = (int)(total / GROUP_SIZE);

    float* base = (float*)d_out;
    float* scale;
    if ((size_t)out_size >= total + (size_t)num_groups) {
        scale = base + ((size_t)out_size - (size_t)num_groups);  // tail of d_out
    } else {
        void* sp = nullptr;
        cudaGetSymbolAddress(&sp, g_scale_scratch);
        scale = (float*)sp;
    }

    // 8 warps/block, 4 groups/warp -> 32 groups per block
    const int groups_per_block = 32;
    const int grid = (num_groups + groups_per_block - 1) / groups_per_block;
    quant_fp8_group_kernel<<<grid, 256>>>(
        (const float4*)x, (float4*)base, scale, num_groups);
}

// round 17
// speedup vs baseline: 1.0156x; 1.0156x over previous
#include <cuda_runtime.h>
#include <cuda_bf16.h>
#include <cstdint>

// Per-token-group (G=128) dynamic fp8-range quantization.
// x: [M, N] fp32 (bf16-rounded values upcast by harness).
// y = clip(x * 448/amax, +-448) fp32; scale = max(amax,1e-4)/448 per group.
// d_out layout: [y (M*N) || scale (M*N/128)] fp32.
//
// FINAL (= R8, measured optimum, reproduced 3x at 82.0us / ~6.35 TB/s):
// flat launch, one warp per TWO groups, both LDG.128 front-batched
// (MLP_p1=2), warp abs-max via single REDUX.MAX on the fabs bit pattern.
// Probed and rejected: MLP=1 (-7%), MLP=4 flat (-4%), MLP=4 reg-capped (0),
// .cs streaming hints (0), persistent grid + prefetch (-13%). DRAM ~80%
// is the mixed 1:1 read:write LTS/HBM ceiling; traffic (514MB) irreducible.

#define GROUP_SIZE 128
#define FP8_MAX 448.0f
#define AMAX_FLOOR 1e-4f

__device__ float g_scale_scratch[1 << 20];  // fallback, never used in practice

__device__ __forceinline__ float max4abs(float4 v) {
    return fmaxf(fmaxf(fabsf(v.x), fabsf(v.y)), fmaxf(fabsf(v.z), fabsf(v.w)));
}

__device__ __forceinline__ float4 scale4(float4 v, float s) {
    float4 o;
    o.x = fminf(fmaxf(v.x * s, -FP8_MAX), FP8_MAX);
    o.y = fminf(fmaxf(v.y * s, -FP8_MAX), FP8_MAX);
    o.z = fminf(fmaxf(v.z * s, -FP8_MAX), FP8_MAX);
    o.w = fminf(fmaxf(v.w * s, -FP8_MAX), FP8_MAX);
    return o;
}

// One warp handles TWO groups (2 x 128 fp32 = 2 x 32 float4).
// Both 16B loads issue back-to-back (MLP_p1 = 2) before any dependency.
// Warp abs-max via REDUX.MAX.U32 on the fabs bit pattern (monotone for >=0).
__global__ void __launch_bounds__(256) quant_fp8_group_kernel(
    const float4* __restrict__ x4,
    float4* __restrict__ y4,
    float* __restrict__ scale,
    int num_groups)
{
    const int warp = threadIdx.x >> 5;
    const int lane = threadIdx.x & 31;
    const int g0 = (blockIdx.x * 8 + warp) * 2;     // first of two groups
    if (g0 >= num_groups) return;

    const size_t base = (size_t)g0 * 32 + (size_t)lane;  // in float4 units

    // Front-batched independent loads (two groups)
    float4 a = x4[base];
    float4 b = x4[base + 32];

    // Per-lane abs-max, then single-instruction warp reduce per group
    unsigned ra = __reduce_max_sync(0xffffffffu, __float_as_uint(max4abs(a)));
    unsigned rb = __reduce_max_sync(0xffffffffu, __float_as_uint(max4abs(b)));

    const float amaxA = fmaxf(__uint_as_float(ra), AMAX_FLOOR);
    const float amaxB = fmaxf(__uint_as_float(rb), AMAX_FLOOR);

    y4[base]      = scale4(a, FP8_MAX / amaxA);
    y4[base + 32] = scale4(b, FP8_MAX / amaxB);

    if (lane == 0) scale[g0] = amaxA / FP8_MAX;
    if (lane == 1 && g0 + 1 < num_groups) scale[g0 + 1] = amaxB / FP8_MAX;
}

extern "C" void kernel_launch(void* const* d_in, const int* in_sizes, int n_in,
                              void* d_out, int out_size)
{
    const float* x = (const float*)d_in[0];
    const size_t total = (size_t)in_sizes[0];          // M * N
    const int num_groups = (int)(total / GROUP_SIZE);

    float* base = (float*)d_out;
    float* scale;
    if ((size_t)out_size >= total + (size_t)num_groups) {
        scale = base + ((size_t)out_size - (size_t)num_groups);  // tail of d_out
    } else {
        void* sp = nullptr;
        cudaGetSymbolAddress(&sp, g_scale_scratch);
        scale = (float*)sp;
    }

    // 8 warps/block, 2 groups/warp -> 16 groups per block
    const int groups_per_block = 16;
    const int grid = (num_groups + groups_per_block - 1) / groups_per_block;
    quant_fp8_group_kernel<<<grid, 256>>>(
        (const float4*)x, (float4*)base, scale, num_groups);
}